// round 2
// baseline (speedup 1.0000x reference)
#include <cuda_runtime.h>
#include <stdint.h>

// Haar DWT level-1 on x: (B=32, L=4096, F=512) fp32.
// out[b, p, f]      = (x[b,2p,f] + x[b,2p+1,f]) / sqrt2   (p in [0,2048))
// out[b, 2048+p, f] = (x[b,2p,f] - x[b,2p+1,f]) / sqrt2
//
// Pure-bandwidth kernel. Each thread handles one pair-row and a 32-byte
// (2 x float4) slice of F: 4 independent LDG.128 batched up front (MLP=4),
// streaming cache hints (no reuse), 4 STG.128 out.

#define B 32
#define L 4096
#define F 512
#define HALF_L (L / 2)
#define F4 (F / 4)                       // 128 float4 per row
#define CHUNKS (F4 / 2)                  // 64 two-float4 chunks per row
#define TOTAL_T (B * HALF_L * CHUNKS)    // 4,194,304 threads

__global__ __launch_bounds__(256) void haar_dwt_kernel(
    const float4* __restrict__ x, float4* __restrict__ out)
{
    int t = blockIdx.x * blockDim.x + threadIdx.x;

    int c  = t & (CHUNKS - 1);           // 0..63  -> float4 index = 2c
    int p  = (t >> 6) & (HALF_L - 1);    // 0..2047
    int b  = t >> 17;                    // 0..31

    long in_base = (long)b * (L * F4) + (long)(2 * p) * F4 + 2 * c;

    // Batch all 4 loads up front (independent, MLP=4), streaming hint.
    float4 x0a = __ldcs(&x[in_base]);
    float4 x0b = __ldcs(&x[in_base + 1]);
    float4 x1a = __ldcs(&x[in_base + F4]);
    float4 x1b = __ldcs(&x[in_base + F4 + 1]);

    const float s = 0.70710678118654752440f;
    float4 ca_a, ca_b, cd_a, cd_b;
    ca_a.x = (x0a.x + x1a.x) * s;  cd_a.x = (x0a.x - x1a.x) * s;
    ca_a.y = (x0a.y + x1a.y) * s;  cd_a.y = (x0a.y - x1a.y) * s;
    ca_a.z = (x0a.z + x1a.z) * s;  cd_a.z = (x0a.z - x1a.z) * s;
    ca_a.w = (x0a.w + x1a.w) * s;  cd_a.w = (x0a.w - x1a.w) * s;
    ca_b.x = (x0b.x + x1b.x) * s;  cd_b.x = (x0b.x - x1b.x) * s;
    ca_b.y = (x0b.y + x1b.y) * s;  cd_b.y = (x0b.y - x1b.y) * s;
    ca_b.z = (x0b.z + x1b.z) * s;  cd_b.z = (x0b.z - x1b.z) * s;
    ca_b.w = (x0b.w + x1b.w) * s;  cd_b.w = (x0b.w - x1b.w) * s;

    long out_base = (long)b * (L * F4) + (long)p * F4 + 2 * c;
    long out_d    = out_base + (long)HALF_L * F4;

    __stcs(&out[out_base],     ca_a);
    __stcs(&out[out_base + 1], ca_b);
    __stcs(&out[out_d],        cd_a);
    __stcs(&out[out_d + 1],    cd_b);
}

extern "C" void kernel_launch(void* const* d_in, const int* in_sizes, int n_in,
                              void* d_out, int out_size)
{
    const float4* x = (const float4*)d_in[0];
    float4* out = (float4*)d_out;

    int threads = 256;
    int blocks = TOTAL_T / threads;      // 16384
    haar_dwt_kernel<<<blocks, threads>>>(x, out);
}

// round 3
// speedup vs baseline: 1.0340x; 1.0340x over previous
#include <cuda_runtime.h>
#include <stdint.h>

// Haar DWT level-1 on x: (B=32, L=4096, F=512) fp32.
// out[b, p, f]      = (x[b,2p,f] + x[b,2p+1,f]) / sqrt2   (p in [0,2048))
// out[b, 2048+p, f] = (x[b,2p,f] - x[b,2p+1,f]) / sqrt2
//
// Fully coalesced (lane = f4, stride-1 float4 within warp).
// MLP=4 per thread via TWO pairs at distant p (p and p+1024), so every
// LDG.128/STG.128 stays a 512B lane-contiguous warp transaction.

#define B 32
#define L 4096
#define F 512
#define HALF_L (L / 2)
#define F4 (F / 4)                        // 128 float4 per row
#define PQ (HALF_L / 2)                   // 1024 pair-indices per thread-group
#define TOTAL_T (B * PQ * F4)             // 4,194,304 threads

__global__ __launch_bounds__(256) void haar_dwt_kernel(
    const float4* __restrict__ x, float4* __restrict__ out)
{
    int t = blockIdx.x * blockDim.x + threadIdx.x;

    int f4 = t & (F4 - 1);                // 0..127 (lane-contiguous)
    int p  = (t >> 7) & (PQ - 1);         // 0..1023
    int b  = t >> 17;                     // 0..31

    long row = (long)F4;
    long base_b = (long)b * (L * F4);

    // pair 0: rows 2p, 2p+1 ; pair 1: rows 2(p+PQ), 2(p+PQ)+1
    long in0 = base_b + (long)(2 * p) * row + f4;
    long in1 = base_b + (long)(2 * (p + PQ)) * row + f4;

    // 4 independent coalesced loads batched up front
    float4 a0 = x[in0];
    float4 a1 = x[in0 + row];
    float4 b0 = x[in1];
    float4 b1 = x[in1 + row];

    const float s = 0.70710678118654752440f;
    float4 ca0, cd0, ca1, cd1;
    ca0.x = (a0.x + a1.x) * s;  cd0.x = (a0.x - a1.x) * s;
    ca0.y = (a0.y + a1.y) * s;  cd0.y = (a0.y - a1.y) * s;
    ca0.z = (a0.z + a1.z) * s;  cd0.z = (a0.z - a1.z) * s;
    ca0.w = (a0.w + a1.w) * s;  cd0.w = (a0.w - a1.w) * s;
    ca1.x = (b0.x + b1.x) * s;  cd1.x = (b0.x - b1.x) * s;
    ca1.y = (b0.y + b1.y) * s;  cd1.y = (b0.y - b1.y) * s;
    ca1.z = (b0.z + b1.z) * s;  cd1.z = (b0.z - b1.z) * s;
    ca1.w = (b0.w + b1.w) * s;  cd1.w = (b0.w - b1.w) * s;

    long outA0 = base_b + (long)p * row + f4;               // approx coeffs pair 0
    long outA1 = base_b + (long)(p + PQ) * row + f4;        // approx coeffs pair 1
    long dOff  = (long)HALF_L * row;                        // detail block offset

    out[outA0]        = ca0;
    out[outA0 + dOff] = cd0;
    out[outA1]        = ca1;
    out[outA1 + dOff] = cd1;
}

extern "C" void kernel_launch(void* const* d_in, const int* in_sizes, int n_in,
                              void* d_out, int out_size)
{
    const float4* x = (const float4*)d_in[0];
    float4* out = (float4*)d_out;

    int threads = 256;
    int blocks = TOTAL_T / threads;       // 16384
    haar_dwt_kernel<<<blocks, threads>>>(x, out);
}